// round 2
// baseline (speedup 1.0000x reference)
#include <cuda_runtime.h>

// MeshConv: g = 5 symmetric features of x[...,0:5]; y = conv1x5(g, W) + b
// x: (4,16,500000,5) f32   W: (16,16,1,5) f32   b: (16,)   y: (4,16,5,499996) f32

#define F_DIM  500000
#define FO     499996
#define CI_N   16
#define CO_N   16
#define N_B    4
#define TILE   128
#define GROWS  132            // TILE + 4 halo rows
#define NTHR   160            // 5h * 4cog * 8fg

typedef unsigned long long ull;

__device__ __forceinline__ void fma2(ull &d, ull a, ull b) {
    asm("fma.rn.f32x2 %0, %1, %2, %0;" : "+l"(d) : "l"(a), "l"(b));
}
__device__ __forceinline__ ull pack2(float lo, float hi) {
    ull r; asm("mov.b64 %0, {%1, %2};" : "=l"(r) : "f"(lo), "f"(hi)); return r;
}
__device__ __forceinline__ float2 unpack2(ull v) {
    float2 r; asm("mov.b64 {%0, %1}, %2;" : "=f"(r.x), "=f"(r.y) : "l"(v)); return r;
}

// dynamic smem layout:
//   gsh : 16ci * 5h * 132 rows floats        = 42240 B
//   wdsh: 16ci * 16co * 5k  ull ({w,w} dup)  = 10240 B
//   bsh : 16 floats                           =    64 B
#define SMEM_BYTES (CI_N*5*GROWS*4 + CI_N*CO_N*5*8 + 64)

extern __shared__ float smem_dyn[];

__global__ __launch_bounds__(NTHR, 3)
void meshconv_kernel(const float* __restrict__ x, const float* __restrict__ W,
                     const float* __restrict__ b, float* __restrict__ y)
{
    float* gsh  = smem_dyn;                              // [ci][h][row]
    ull*   wdsh = (ull*)(smem_dyn + CI_N*5*GROWS);       // [ci][co][k] duplicated pairs
    float* bsh  = (float*)(wdsh + CI_N*CO_N*5);          // [co]

    const int tid = threadIdx.x;
    const int n   = blockIdx.y;
    const int f0  = blockIdx.x * TILE;

    // ---- preload W (duplicated into {w,w} pairs) + bias ----
    for (int idx = tid; idx < CO_N*CI_N*5; idx += NTHR) {
        int co = idx / (CI_N*5);
        int r  = idx % (CI_N*5);
        int ci = r / 5, k = r % 5;
        float w = W[idx];                                // W[(co*16+ci)*5+k]
        wdsh[(ci*CO_N + co)*5 + k] = pack2(w, w);
    }
    if (tid < CO_N) bsh[tid] = b[tid];

    // ---- build g tile in smem (x read exactly once from DRAM) ----
    for (int id = tid; id < CI_N*GROWS; id += NTHR) {
        int ci  = id / GROWS;
        int row = id % GROWS;
        int f   = f0 + row;
        float v0 = 0.f, v1 = 0.f, v2 = 0.f, v3 = 0.f, v4 = 0.f;
        if (f < F_DIM) {
            const float* xp = x + ((n*CI_N + ci)*F_DIM + f)*5;
            v0 = xp[0]; v1 = xp[1]; v2 = xp[2]; v3 = xp[3]; v4 = xp[4];
        }
        float* gp = gsh + ci*5*GROWS;
        gp[0*GROWS + row] = v0;
        gp[1*GROWS + row] = v1 + v3;
        gp[2*GROWS + row] = v2 + v4;
        gp[3*GROWS + row] = fabsf(v1 - v3);
        gp[4*GROWS + row] = fabsf(v2 - v4);
    }
    __syncthreads();

    // ---- compute: thread = (h, 4-co group, f-group), 4co x 16f outputs ----
    const int h    = tid >> 5;          // 0..4 (whole warp shares h)
    const int lane = tid & 31;
    const int cog  = lane >> 3;         // 0..3
    const int fg   = lane & 7;          // 0..7
    const int co0  = cog * 4;
    const int fbase = fg * 2;           // thread's f = fbase + j*16, j=0..7

    ull acc[4][8];
    #pragma unroll
    for (int c = 0; c < 4; ++c) {
        float bb = bsh[co0 + c];
        ull bp = pack2(bb, bb);
        #pragma unroll
        for (int j = 0; j < 8; ++j) acc[c][j] = bp;
    }

    #pragma unroll 1
    for (int ci = 0; ci < CI_N; ++ci) {
        const ull* wp = wdsh + (ci*CO_N + co0)*5;
        ull wr[4][5];
        #pragma unroll
        for (int c = 0; c < 4; ++c)
            #pragma unroll
            for (int k = 0; k < 5; ++k)
                wr[c][k] = wp[c*5 + k];

        const float* grow = gsh + (ci*5 + h)*GROWS;
        #pragma unroll
        for (int j = 0; j < 8; ++j) {
            const float2* gp = (const float2*)(grow + fbase + j*16);
            float2 ga = gp[0], gb = gp[1], gc = gp[2];     // g[f..f+5], conflict-free LDS.64
            ull e0 = pack2(ga.x, ga.y);
            ull e1 = pack2(gb.x, gb.y);
            ull e2 = pack2(gc.x, gc.y);
            ull p1 = pack2(ga.y, gb.x);                    // odd-offset window pairs
            ull p3 = pack2(gb.y, gc.x);
            #pragma unroll
            for (int c = 0; c < 4; ++c) {
                fma2(acc[c][j], e0, wr[c][0]);
                fma2(acc[c][j], p1, wr[c][1]);
                fma2(acc[c][j], e1, wr[c][2]);
                fma2(acc[c][j], p3, wr[c][3]);
                fma2(acc[c][j], e2, wr[c][4]);
            }
        }
    }

    // ---- store (float2, coalesced in 64B runs per co-group) ----
    #pragma unroll
    for (int c = 0; c < 4; ++c) {
        float* ybase = y + (((n*CO_N + co0 + c)*5 + h) * FO);
        #pragma unroll
        for (int j = 0; j < 8; ++j) {
            int f = f0 + fbase + j*16;
            if (f < FO) {                 // FO even, f even -> pair fully in range
                float2 v = unpack2(acc[c][j]);
                *(float2*)(ybase + f) = v;
            }
        }
    }
}

extern "C" void kernel_launch(void* const* d_in, const int* in_sizes, int n_in,
                              void* d_out, int out_size)
{
    (void)in_sizes; (void)n_in; (void)out_size;
    const float* x = (const float*)d_in[0];
    const float* W = (const float*)d_in[1];
    const float* b = (const float*)d_in[2];
    float*       y = (float*)d_out;

    cudaFuncSetAttribute(meshconv_kernel,
                         cudaFuncAttributeMaxDynamicSharedMemorySize, SMEM_BYTES);

    dim3 grid((FO + TILE - 1) / TILE, N_B);
    meshconv_kernel<<<grid, NTHR, SMEM_BYTES>>>(x, W, b, y);
}